// round 3
// baseline (speedup 1.0000x reference)
#include <cuda_runtime.h>
#include <math.h>

// LSTM_38646115729591 — 2-layer bidirectional LSTM, fp32.
// T=512, B=64, D=512, H=512. Output [T,B,2H] fp32.

#define T_LEN 512
#define BATCH 64
#define HID   512
#define G4    2048
#define MROWS (T_LEN * BATCH)   // 32768
#define NBLK  128               // persistent grid (<=148 SMs -> co-resident)

#define W_STRIDE 516            // 512 + 4 pad  (516 % 32 == 4 -> conflict-free)
#define H_STRIDE 132            // 128 + 4 pad
#define SMEM_FLOATS (32 * W_STRIDE + 2 * 64 * H_STRIDE)   // 33408
#define SMEM_BYTES  (SMEM_FLOATS * 4)                     // 133632

typedef unsigned long long ull;

// ---- static device scratch (no runtime allocation allowed) ----
__device__ float g_xg_f[(size_t)MROWS * G4];       // 256 MB
__device__ float g_xg_b[(size_t)MROWS * G4];       // 256 MB
__device__ float g_l0[(size_t)MROWS * 2 * HID];    // 128 MB (layer0 output)
__device__ float g_h[2][2][BATCH * HID];           // [dir][ping][b*H]
__device__ unsigned g_cnt;
__device__ unsigned g_gen;

// ---- f32x2 helpers (FFMA2: 2x fp32 FMA rate on sm_103a) ----
__device__ __forceinline__ ull ffma2(ull a, ull b, ull c) {
    ull d;
    asm("fma.rn.f32x2 %0, %1, %2, %3;" : "=l"(d) : "l"(a), "l"(b), "l"(c));
    return d;
}
__device__ __forceinline__ float2 unpk(ull v) {
    float2 r;
    asm("mov.b64 {%0, %1}, %2;" : "=f"(r.x), "=f"(r.y) : "l"(v));
    return r;
}
__device__ __forceinline__ float sigf(float x) { return 1.0f / (1.0f + __expf(-x)); }

// =====================================================================
// SGEMM: C[M,N] = A[M,K] @ B[N,K]^T + b1[N] + b2[N]
// BM=BN=128, BK=8, 256 threads, 8x8 per-thread tile, FFMA2 accumulators.
// A values stored PRE-DUPLICATED in smem (pair lanes) -> no dup MOVs in loop.
// =====================================================================
__global__ __launch_bounds__(256) void sgemm_bias(
    const float* __restrict__ A, const float* __restrict__ B,
    const float* __restrict__ b1, const float* __restrict__ b2,
    float* __restrict__ C, int K, int N)
{
    __shared__ float As2[8][264];   // [k][2*m .. 2*m+1] duplicated pairs
    __shared__ float Bs[8][132];

    const int tid  = threadIdx.x;
    const int bm   = blockIdx.y * 128;
    const int bn   = blockIdx.x * 128;
    const int lrow = tid >> 1;            // 0..127
    const int lk   = (tid & 1) << 2;      // 0 or 4
    const int tx   = tid & 15;
    const int ty   = tid >> 4;

    const float* Ap = A + (size_t)(bm + lrow) * K + lk;
    const float* Bp = B + (size_t)(bn + lrow) * K + lk;

    ull acc[8][4];
#pragma unroll
    for (int i = 0; i < 8; i++)
#pragma unroll
        for (int j = 0; j < 4; j++) acc[i][j] = 0ULL;

    float4 av = *(const float4*)Ap;
    float4 bv = *(const float4*)Bp;

    for (int k0 = 0; k0 < K; k0 += 8) {
        *(float2*)&As2[lk + 0][lrow * 2] = make_float2(av.x, av.x);
        *(float2*)&As2[lk + 1][lrow * 2] = make_float2(av.y, av.y);
        *(float2*)&As2[lk + 2][lrow * 2] = make_float2(av.z, av.z);
        *(float2*)&As2[lk + 3][lrow * 2] = make_float2(av.w, av.w);
        Bs[lk + 0][lrow] = bv.x; Bs[lk + 1][lrow] = bv.y;
        Bs[lk + 2][lrow] = bv.z; Bs[lk + 3][lrow] = bv.w;
        __syncthreads();
        if (k0 + 8 < K) {
            av = *(const float4*)(Ap + k0 + 8);
            bv = *(const float4*)(Bp + k0 + 8);
        }
#pragma unroll
        for (int kk = 0; kk < 8; kk++) {
            const ulonglong2 a0 = *(const ulonglong2*)&As2[kk][ty * 8];
            const ulonglong2 a1 = *(const ulonglong2*)&As2[kk][ty * 8 + 4];
            const ulonglong2 a2 = *(const ulonglong2*)&As2[kk][128 + ty * 8];
            const ulonglong2 a3 = *(const ulonglong2*)&As2[kk][128 + ty * 8 + 4];
            const ulonglong2 p0 = *(const ulonglong2*)&Bs[kk][tx * 4];
            const ulonglong2 p1 = *(const ulonglong2*)&Bs[kk][64 + tx * 4];
            ull ad[8];
            ad[0] = a0.x; ad[1] = a0.y; ad[2] = a1.x; ad[3] = a1.y;
            ad[4] = a2.x; ad[5] = a2.y; ad[6] = a3.x; ad[7] = a3.y;
#pragma unroll
            for (int i = 0; i < 8; i++) {
                acc[i][0] = ffma2(ad[i], p0.x, acc[i][0]);
                acc[i][1] = ffma2(ad[i], p0.y, acc[i][1]);
                acc[i][2] = ffma2(ad[i], p1.x, acc[i][2]);
                acc[i][3] = ffma2(ad[i], p1.y, acc[i][3]);
            }
        }
        __syncthreads();
    }

#pragma unroll
    for (int i = 0; i < 8; i++) {
        const int m = bm + ((i < 4) ? (ty * 4 + i) : (64 + ty * 4 + (i - 4)));
#pragma unroll
        for (int j = 0; j < 4; j++) {
            const int n = bn + ((j < 2) ? (tx * 4 + 2 * j) : (64 + tx * 4 + 2 * (j - 2)));
            float2 v = unpk(acc[i][j]);
            v.x += b1[n] + b2[n];
            v.y += b1[n + 1] + b2[n + 1];
            *(float2*)&C[(size_t)m * N + n] = v;
        }
    }
}

// =====================================================================
// init_state: zero h ping-pong buffers + barrier state
// =====================================================================
__global__ void init_state()
{
    const int i = blockIdx.x * blockDim.x + threadIdx.x;
    if (i < BATCH * HID) {
        g_h[0][0][i] = 0.0f; g_h[0][1][i] = 0.0f;
        g_h[1][0][i] = 0.0f; g_h[1][1][i] = 0.0f;
    }
    if (i == 0) { g_cnt = 0u; g_gen = 0u; }
}

// =====================================================================
// grid barrier across all NBLK co-resident blocks (release/acquire)
// =====================================================================
__device__ __forceinline__ void grid_barrier()
{
    __syncthreads();
    if (threadIdx.x == 0) {
        __threadfence();                               // release my writes
        const unsigned gen = *(volatile unsigned*)&g_gen;
        __threadfence();                               // order gen-read before arrive
        if (atomicAdd(&g_cnt, 1u) == NBLK - 1u) {
            atomicExch(&g_cnt, 0u);
            __threadfence();
            *(volatile unsigned*)&g_gen = gen + 1u;    // release all
        } else {
            while (*(volatile unsigned*)&g_gen == gen) { }
        }
        __threadfence();                               // acquire (flushes L1D too)
    }
    __syncthreads();
}

// =====================================================================
// Persistent recurrence: all 512 steps of one layer, both directions.
// 128 blocks: dir = bx/64, hb = bx%64 (8 h-units x 4 gates = 32 w_hh rows).
// W slice lives in smem for the whole kernel; h staged per step in
// double-buffered 128-col chunks; cell state in registers.
// Thread (u = tid%8, bp = tid/8): 2 batches x 4 gates, k-paired FFMA2.
// =====================================================================
__global__ __launch_bounds__(256) void lstm_persist(
    const float* __restrict__ xg_f, const float* __restrict__ xg_b,
    const float* __restrict__ whh_f, const float* __restrict__ whh_b,
    float* __restrict__ out)
{
    extern __shared__ float sm[];
    float (*wsm)[W_STRIDE] = (float(*)[W_STRIDE])sm;
    float (*hA)[H_STRIDE]  = (float(*)[H_STRIDE])(sm + 32 * W_STRIDE);
    float (*hB)[H_STRIDE]  = (float(*)[H_STRIDE])(sm + 32 * W_STRIDE + 64 * H_STRIDE);

    const int tid = threadIdx.x;
    const int dir = blockIdx.x >> 6;
    const int hb  = blockIdx.x & 63;
    const int u0  = hb * 8;
    const int u   = tid & 7;
    const int bp  = tid >> 3;                   // 0..31
    const int uu  = u0 + u;

    const float* xg  = dir ? xg_b : xg_f;
    const float* whh = dir ? whh_b : whh_f;

    // ---- load W slice once: rows {g*512 + u0 + j}, j=0..7, g=0..3 ----
#pragma unroll
    for (int i = tid; i < 32 * 128; i += 256) {     // float4 index
        const int rr = i >> 7;                      // 0..31 (= g*8 + j)
        const int c  = (i & 127) << 2;
        const int grow = (rr >> 3) * HID + u0 + (rr & 7);
        *(float4*)&wsm[rr][c] = *(const float4*)&whh[(size_t)grow * HID + c];
    }
    __syncthreads();

    float cp0 = 0.0f, cp1 = 0.0f;                   // cell state in registers
    const int bb0 = 2 * bp, bb1 = 2 * bp + 1;

    for (int t = 0; t < T_LEN; t++) {
        const int t_eff = dir ? (T_LEN - 1 - t) : t;
        const int ping  = t & 1;
        const float* hprev = g_h[dir][ping];
        float*       hnext = g_h[dir][ping ^ 1];

        // prefetch xg rows for this step (DRAM latency hides under compute)
        float xr[2][4];
#pragma unroll
        for (int g = 0; g < 4; g++) {
            xr[0][g] = __ldg(&xg[((size_t)t_eff * BATCH + bb0) * G4 + g * HID + uu]);
            xr[1][g] = __ldg(&xg[((size_t)t_eff * BATCH + bb1) * G4 + g * HID + uu]);
        }

        // stage chunk 0
        float4 v[8];
#pragma unroll
        for (int r = 0; r < 8; r++) {
            const int idx = tid + r * 256;          // 0..2047
            const int b   = idx >> 5;
            const int cc  = (idx & 31) << 2;
            v[r] = __ldcg((const float4*)&hprev[b * HID + cc]);
        }
#pragma unroll
        for (int r = 0; r < 8; r++) {
            const int idx = tid + r * 256;
            *(float4*)&hA[idx >> 5][(idx & 31) << 2] = v[r];
        }
        __syncthreads();

        ull acc[2][4];
#pragma unroll
        for (int g = 0; g < 4; g++) { acc[0][g] = 0ULL; acc[1][g] = 0ULL; }

#pragma unroll
        for (int c = 0; c < 4; c++) {
            float (*cur)[H_STRIDE] = (c & 1) ? hB : hA;
            float (*nxt)[H_STRIDE] = (c & 1) ? hA : hB;
            if (c < 3) {
#pragma unroll
                for (int r = 0; r < 8; r++) {
                    const int idx = tid + r * 256;
                    const int b   = idx >> 5;
                    const int cc  = (idx & 31) << 2;
                    v[r] = __ldcg((const float4*)&hprev[b * HID + (c + 1) * 128 + cc]);
                }
            }
#pragma unroll
            for (int k4 = 0; k4 < 32; k4++) {
                const ulonglong2 h0 = *(const ulonglong2*)&cur[bb0][k4 * 4];
                const ulonglong2 h1 = *(const ulonglong2*)&cur[bb1][k4 * 4];
#pragma unroll
                for (int g = 0; g < 4; g++) {
                    const ulonglong2 wv =
                        *(const ulonglong2*)&wsm[g * 8 + u][c * 128 + k4 * 4];
                    acc[0][g] = ffma2(h0.x, wv.x, acc[0][g]);
                    acc[0][g] = ffma2(h0.y, wv.y, acc[0][g]);
                    acc[1][g] = ffma2(h1.x, wv.x, acc[1][g]);
                    acc[1][g] = ffma2(h1.y, wv.y, acc[1][g]);
                }
            }
            if (c < 3) {
#pragma unroll
                for (int r = 0; r < 8; r++) {
                    const int idx = tid + r * 256;
                    *(float4*)&nxt[idx >> 5][(idx & 31) << 2] = v[r];
                }
            }
            __syncthreads();
        }

        // ---- cell update (2 cells/thread), c-state in registers ----
        {
            const float2 vi = unpk(acc[0][0]), vf = unpk(acc[0][1]);
            const float2 vg = unpk(acc[0][2]), vo = unpk(acc[0][3]);
            const float gi = vi.x + vi.y + xr[0][0];
            const float gf = vf.x + vf.y + xr[0][1];
            const float gg = vg.x + vg.y + xr[0][2];
            const float go = vo.x + vo.y + xr[0][3];
            cp0 = sigf(gf) * cp0 + sigf(gi) * tanhf(gg);
            const float hn = sigf(go) * tanhf(cp0);
            __stcg(&hnext[bb0 * HID + uu], hn);
            out[((size_t)t_eff * BATCH + bb0) * (2 * HID) + dir * HID + uu] = hn;
        }
        {
            const float2 vi = unpk(acc[1][0]), vf = unpk(acc[1][1]);
            const float2 vg = unpk(acc[1][2]), vo = unpk(acc[1][3]);
            const float gi = vi.x + vi.y + xr[1][0];
            const float gf = vf.x + vf.y + xr[1][1];
            const float gg = vg.x + vg.y + xr[1][2];
            const float go = vo.x + vo.y + xr[1][3];
            cp1 = sigf(gf) * cp1 + sigf(gi) * tanhf(gg);
            const float hn = sigf(go) * tanhf(cp1);
            __stcg(&hnext[bb1 * HID + uu], hn);
            out[((size_t)t_eff * BATCH + bb1) * (2 * HID) + dir * HID + uu] = hn;
        }

        grid_barrier();
    }
}

// =====================================================================
// host
// =====================================================================
extern "C" void kernel_launch(void* const* d_in, const int* in_sizes, int n_in,
                              void* d_out, int out_size)
{
    const float* x       = (const float*)d_in[0];
    const float* w_ih0_f = (const float*)d_in[1];
    const float* w_hh0_f = (const float*)d_in[2];
    const float* b_ih0_f = (const float*)d_in[3];
    const float* b_hh0_f = (const float*)d_in[4];
    const float* w_ih0_b = (const float*)d_in[5];
    const float* w_hh0_b = (const float*)d_in[6];
    const float* b_ih0_b = (const float*)d_in[7];
    const float* b_hh0_b = (const float*)d_in[8];
    const float* w_ih1_f = (const float*)d_in[9];
    const float* w_hh1_f = (const float*)d_in[10];
    const float* b_ih1_f = (const float*)d_in[11];
    const float* b_hh1_f = (const float*)d_in[12];
    const float* w_ih1_b = (const float*)d_in[13];
    const float* w_hh1_b = (const float*)d_in[14];
    const float* b_ih1_b = (const float*)d_in[15];
    const float* b_hh1_b = (const float*)d_in[16];
    float* out = (float*)d_out;

    float *xg_f, *xg_b, *l0;
    cudaGetSymbolAddress((void**)&xg_f, g_xg_f);
    cudaGetSymbolAddress((void**)&xg_b, g_xg_b);
    cudaGetSymbolAddress((void**)&l0,   g_l0);

    static int smem_set = 0;
    if (!smem_set) {
        cudaFuncSetAttribute(lstm_persist,
                             cudaFuncAttributeMaxDynamicSharedMemorySize, SMEM_BYTES);
        smem_set = 1;
    }

    const dim3 gemm_grid(G4 / 128, MROWS / 128);   // (16, 256)

    // ---- layer 0 ----
    sgemm_bias<<<gemm_grid, 256>>>(x, w_ih0_f, b_ih0_f, b_hh0_f, xg_f, 512, G4);
    sgemm_bias<<<gemm_grid, 256>>>(x, w_ih0_b, b_ih0_b, b_hh0_b, xg_b, 512, G4);
    init_state<<<128, 256>>>();
    lstm_persist<<<NBLK, 256, SMEM_BYTES>>>(xg_f, xg_b, w_hh0_f, w_hh0_b, l0);

    // ---- layer 1 (K = 1024) ----
    sgemm_bias<<<gemm_grid, 256>>>(l0, w_ih1_f, b_ih1_f, b_hh1_f, xg_f, 1024, G4);
    sgemm_bias<<<gemm_grid, 256>>>(l0, w_ih1_b, b_ih1_b, b_hh1_b, xg_b, 1024, G4);
    init_state<<<128, 256>>>();
    lstm_persist<<<NBLK, 256, SMEM_BYTES>>>(xg_f, xg_b, w_hh1_f, w_hh1_b, out);
}

// round 4
// speedup vs baseline: 1.0414x; 1.0414x over previous
#include <cuda_runtime.h>
#include <math.h>

// LSTM_38646115729591 — 2-layer bidirectional LSTM, fp32.
// T=512, B=64, D=512, H=512. Output [T,B,2H] fp32.

#define T_LEN 512
#define BATCH 64
#define HID   512
#define G4    2048
#define MROWS (T_LEN * BATCH)   // 32768
#define NBLK  128               // persistent grid (<=148 SMs -> co-resident)

#define W_STRIDE 516            // 512 + 4 pad (conflict-free rows)
#define SMEM_FLOATS ((32 + 64) * W_STRIDE)     // W slice + full h stage
#define SMEM_BYTES  (SMEM_FLOATS * 4)          // 198144 B (< 227KB opt-in)

typedef unsigned long long ull;

// ---- static device scratch (no runtime allocation allowed) ----
__device__ float g_xg_f[(size_t)MROWS * G4];       // 256 MB
__device__ float g_xg_b[(size_t)MROWS * G4];       // 256 MB
__device__ float g_l0[(size_t)MROWS * 2 * HID];    // 128 MB (layer0 output)
__device__ float g_h[2][2][BATCH * HID];           // [dir][ping][b*H]
__device__ unsigned g_cnt;
__device__ unsigned g_gen;

// ---- f32x2 helpers (FFMA2: 2x fp32 FMA rate on sm_103a) ----
__device__ __forceinline__ ull ffma2(ull a, ull b, ull c) {
    ull d;
    asm("fma.rn.f32x2 %0, %1, %2, %3;" : "=l"(d) : "l"(a), "l"(b), "l"(c));
    return d;
}
__device__ __forceinline__ float2 unpk(ull v) {
    float2 r;
    asm("mov.b64 {%0, %1}, %2;" : "=f"(r.x), "=f"(r.y) : "l"(v));
    return r;
}
__device__ __forceinline__ float sigf(float x) { return 1.0f / (1.0f + __expf(-x)); }

// =====================================================================
// SGEMM: C[M,N] = A[M,K] @ B[N,K]^T + b1[N] + b2[N]
// BM=BN=128, BK=8, 256 threads, 8x8 per-thread tile, FFMA2 accumulators.
// =====================================================================
__global__ __launch_bounds__(256) void sgemm_bias(
    const float* __restrict__ A, const float* __restrict__ B,
    const float* __restrict__ b1, const float* __restrict__ b2,
    float* __restrict__ C, int K, int N)
{
    __shared__ float As2[8][264];   // [k][2*m .. 2*m+1] duplicated pairs
    __shared__ float Bs[8][132];

    const int tid  = threadIdx.x;
    const int bm   = blockIdx.y * 128;
    const int bn   = blockIdx.x * 128;
    const int lrow = tid >> 1;
    const int lk   = (tid & 1) << 2;
    const int tx   = tid & 15;
    const int ty   = tid >> 4;

    const float* Ap = A + (size_t)(bm + lrow) * K + lk;
    const float* Bp = B + (size_t)(bn + lrow) * K + lk;

    ull acc[8][4];
#pragma unroll
    for (int i = 0; i < 8; i++)
#pragma unroll
        for (int j = 0; j < 4; j++) acc[i][j] = 0ULL;

    float4 av = *(const float4*)Ap;
    float4 bv = *(const float4*)Bp;

    for (int k0 = 0; k0 < K; k0 += 8) {
        *(float2*)&As2[lk + 0][lrow * 2] = make_float2(av.x, av.x);
        *(float2*)&As2[lk + 1][lrow * 2] = make_float2(av.y, av.y);
        *(float2*)&As2[lk + 2][lrow * 2] = make_float2(av.z, av.z);
        *(float2*)&As2[lk + 3][lrow * 2] = make_float2(av.w, av.w);
        Bs[lk + 0][lrow] = bv.x; Bs[lk + 1][lrow] = bv.y;
        Bs[lk + 2][lrow] = bv.z; Bs[lk + 3][lrow] = bv.w;
        __syncthreads();
        if (k0 + 8 < K) {
            av = *(const float4*)(Ap + k0 + 8);
            bv = *(const float4*)(Bp + k0 + 8);
        }
#pragma unroll
        for (int kk = 0; kk < 8; kk++) {
            const ulonglong2 a0 = *(const ulonglong2*)&As2[kk][ty * 8];
            const ulonglong2 a1 = *(const ulonglong2*)&As2[kk][ty * 8 + 4];
            const ulonglong2 a2 = *(const ulonglong2*)&As2[kk][128 + ty * 8];
            const ulonglong2 a3 = *(const ulonglong2*)&As2[kk][128 + ty * 8 + 4];
            const ulonglong2 p0 = *(const ulonglong2*)&Bs[kk][tx * 4];
            const ulonglong2 p1 = *(const ulonglong2*)&Bs[kk][64 + tx * 4];
            ull ad[8];
            ad[0] = a0.x; ad[1] = a0.y; ad[2] = a1.x; ad[3] = a1.y;
            ad[4] = a2.x; ad[5] = a2.y; ad[6] = a3.x; ad[7] = a3.y;
#pragma unroll
            for (int i = 0; i < 8; i++) {
                acc[i][0] = ffma2(ad[i], p0.x, acc[i][0]);
                acc[i][1] = ffma2(ad[i], p0.y, acc[i][1]);
                acc[i][2] = ffma2(ad[i], p1.x, acc[i][2]);
                acc[i][3] = ffma2(ad[i], p1.y, acc[i][3]);
            }
        }
        __syncthreads();
    }

#pragma unroll
    for (int i = 0; i < 8; i++) {
        const int m = bm + ((i < 4) ? (ty * 4 + i) : (64 + ty * 4 + (i - 4)));
#pragma unroll
        for (int j = 0; j < 4; j++) {
            const int n = bn + ((j < 2) ? (tx * 4 + 2 * j) : (64 + tx * 4 + 2 * (j - 2)));
            float2 v = unpk(acc[i][j]);
            v.x += b1[n] + b2[n];
            v.y += b1[n + 1] + b2[n + 1];
            *(float2*)&C[(size_t)m * N + n] = v;
        }
    }
}

// =====================================================================
// init_state
// =====================================================================
__global__ void init_state()
{
    const int i = blockIdx.x * blockDim.x + threadIdx.x;
    if (i < BATCH * HID) {
        g_h[0][0][i] = 0.0f; g_h[0][1][i] = 0.0f;
        g_h[1][0][i] = 0.0f; g_h[1][1][i] = 0.0f;
    }
    if (i == 0) { g_cnt = 0u; g_gen = 0u; }
}

// =====================================================================
// grid barrier across all NBLK co-resident blocks (release/acquire)
// =====================================================================
__device__ __forceinline__ void grid_barrier()
{
    __syncthreads();
    if (threadIdx.x == 0) {
        __threadfence();                               // release my writes
        const unsigned gen = *(volatile unsigned*)&g_gen;
        __threadfence();
        if (atomicAdd(&g_cnt, 1u) == NBLK - 1u) {
            atomicExch(&g_cnt, 0u);
            __threadfence();
            *(volatile unsigned*)&g_gen = gen + 1u;    // release all
        } else {
            while (*(volatile unsigned*)&g_gen == gen) { }
        }
        __threadfence();                               // acquire
    }
    __syncthreads();
}

// =====================================================================
// Persistent recurrence: all 512 steps of one layer, both directions.
// 128 blocks: dir = bx/64, hb = bx%64 (8 h-units x 4 gates = 32 w_hh rows).
// W slice resident in smem for the whole kernel; full h (64x512) staged
// per step; inner loop software-pipelined (LDS -> use distance = 16 FFMA2).
// Thread (u = tid%8, bp = tid/8): 2 batches x 4 gates, k-paired FFMA2.
// =====================================================================
__global__ __launch_bounds__(256) void lstm_persist(
    const float* __restrict__ xg_f, const float* __restrict__ xg_b,
    const float* __restrict__ whh_f, const float* __restrict__ whh_b,
    float* __restrict__ out)
{
    extern __shared__ float sm[];
    float (*wsm)[W_STRIDE] = (float(*)[W_STRIDE])sm;
    float (*hsm)[W_STRIDE] = (float(*)[W_STRIDE])(sm + 32 * W_STRIDE);

    const int tid = threadIdx.x;
    const int dir = blockIdx.x >> 6;
    const int hb  = blockIdx.x & 63;
    const int u0  = hb * 8;
    const int u   = tid & 7;
    const int bp  = tid >> 3;                   // 0..31
    const int uu  = u0 + u;
    const int bb0 = 2 * bp, bb1 = 2 * bp + 1;

    const float* xg  = dir ? xg_b : xg_f;
    const float* whh = dir ? whh_b : whh_f;

    // ---- load W slice once: rows {g*512 + u0 + j}, j=0..7, g=0..3 ----
    for (int i = tid; i < 32 * 128; i += 256) {     // float4 index
        const int rr = i >> 7;
        const int c  = (i & 127) << 2;
        const int grow = (rr >> 3) * HID + u0 + (rr & 7);
        *(float4*)&wsm[rr][c] = *(const float4*)&whh[(size_t)grow * HID + c];
    }
    __syncthreads();

    float cp0 = 0.0f, cp1 = 0.0f;                   // cell state in registers

    for (int t = 0; t < T_LEN; t++) {
        const int t_eff = dir ? (T_LEN - 1 - t) : t;
        const int ping  = t & 1;
        const float* hprev = g_h[dir][ping];
        float*       hnext = g_h[dir][ping ^ 1];

        // prefetch xg rows for this step
        float xr[2][4];
#pragma unroll
        for (int g = 0; g < 4; g++) {
            xr[0][g] = __ldg(&xg[((size_t)t_eff * BATCH + bb0) * G4 + g * HID + uu]);
            xr[1][g] = __ldg(&xg[((size_t)t_eff * BATCH + bb1) * G4 + g * HID + uu]);
        }

        // ---- stage full h (64 x 512): 8192 float4, 32 per thread ----
#pragma unroll
        for (int rr = 0; rr < 4; rr++) {
            float4 v[8];
#pragma unroll
            for (int r = 0; r < 8; r++) {
                const int idx = tid + (rr * 8 + r) * 256;       // 0..8191
                v[r] = __ldcg((const float4*)&hprev[idx * 4]);  // coalesced
            }
#pragma unroll
            for (int r = 0; r < 8; r++) {
                const int idx = tid + (rr * 8 + r) * 256;
                *(float4*)&hsm[idx >> 7][(idx & 127) << 2] = v[r];
            }
        }
        __syncthreads();

        // ---- software-pipelined dot products over k = 0..511 ----
        ull acc[2][4];
#pragma unroll
        for (int g = 0; g < 4; g++) { acc[0][g] = 0ULL; acc[1][g] = 0ULL; }

        ulonglong2 h0n = *(const ulonglong2*)&hsm[bb0][0];
        ulonglong2 h1n = *(const ulonglong2*)&hsm[bb1][0];
        ulonglong2 w0n = *(const ulonglong2*)&wsm[0 * 8 + u][0];
        ulonglong2 w1n = *(const ulonglong2*)&wsm[1 * 8 + u][0];
        ulonglong2 w2n = *(const ulonglong2*)&wsm[2 * 8 + u][0];
        ulonglong2 w3n = *(const ulonglong2*)&wsm[3 * 8 + u][0];

#pragma unroll 4
        for (int k4 = 0; k4 < 128; k4++) {
            const ulonglong2 h0 = h0n, h1 = h1n;
            const ulonglong2 w0 = w0n, w1 = w1n, w2 = w2n, w3 = w3n;
            const int kn = ((k4 + 1) & 127) * 4;    // wrap: harmless reload
            h0n = *(const ulonglong2*)&hsm[bb0][kn];
            h1n = *(const ulonglong2*)&hsm[bb1][kn];
            w0n = *(const ulonglong2*)&wsm[0 * 8 + u][kn];
            w1n = *(const ulonglong2*)&wsm[1 * 8 + u][kn];
            w2n = *(const ulonglong2*)&wsm[2 * 8 + u][kn];
            w3n = *(const ulonglong2*)&wsm[3 * 8 + u][kn];
            acc[0][0] = ffma2(h0.x, w0.x, acc[0][0]);
            acc[1][0] = ffma2(h1.x, w0.x, acc[1][0]);
            acc[0][1] = ffma2(h0.x, w1.x, acc[0][1]);
            acc[1][1] = ffma2(h1.x, w1.x, acc[1][1]);
            acc[0][2] = ffma2(h0.x, w2.x, acc[0][2]);
            acc[1][2] = ffma2(h1.x, w2.x, acc[1][2]);
            acc[0][3] = ffma2(h0.x, w3.x, acc[0][3]);
            acc[1][3] = ffma2(h1.x, w3.x, acc[1][3]);
            acc[0][0] = ffma2(h0.y, w0.y, acc[0][0]);
            acc[1][0] = ffma2(h1.y, w0.y, acc[1][0]);
            acc[0][1] = ffma2(h0.y, w1.y, acc[0][1]);
            acc[1][1] = ffma2(h1.y, w1.y, acc[1][1]);
            acc[0][2] = ffma2(h0.y, w2.y, acc[0][2]);
            acc[1][2] = ffma2(h1.y, w2.y, acc[1][2]);
            acc[0][3] = ffma2(h0.y, w3.y, acc[0][3]);
            acc[1][3] = ffma2(h1.y, w3.y, acc[1][3]);
        }

        // ---- cell update (2 cells/thread), c-state in registers ----
        {
            const float2 vi = unpk(acc[0][0]), vf = unpk(acc[0][1]);
            const float2 vg = unpk(acc[0][2]), vo = unpk(acc[0][3]);
            const float gi = vi.x + vi.y + xr[0][0];
            const float gf = vf.x + vf.y + xr[0][1];
            const float gg = vg.x + vg.y + xr[0][2];
            const float go = vo.x + vo.y + xr[0][3];
            cp0 = sigf(gf) * cp0 + sigf(gi) * tanhf(gg);
            const float hn = sigf(go) * tanhf(cp0);
            __stcg(&hnext[bb0 * HID + uu], hn);
            out[((size_t)t_eff * BATCH + bb0) * (2 * HID) + dir * HID + uu] = hn;
        }
        {
            const float2 vi = unpk(acc[1][0]), vf = unpk(acc[1][1]);
            const float2 vg = unpk(acc[1][2]), vo = unpk(acc[1][3]);
            const float gi = vi.x + vi.y + xr[1][0];
            const float gf = vf.x + vf.y + xr[1][1];
            const float gg = vg.x + vg.y + xr[1][2];
            const float go = vo.x + vo.y + xr[1][3];
            cp1 = sigf(gf) * cp1 + sigf(gi) * tanhf(gg);
            const float hn = sigf(go) * tanhf(cp1);
            __stcg(&hnext[bb1 * HID + uu], hn);
            out[((size_t)t_eff * BATCH + bb1) * (2 * HID) + dir * HID + uu] = hn;
        }

        grid_barrier();   // leading __syncthreads also protects hsm reuse
    }
}

// =====================================================================
// host
// =====================================================================
extern "C" void kernel_launch(void* const* d_in, const int* in_sizes, int n_in,
                              void* d_out, int out_size)
{
    const float* x       = (const float*)d_in[0];
    const float* w_ih0_f = (const float*)d_in[1];
    const float* w_hh0_f = (const float*)d_in[2];
    const float* b_ih0_f = (const float*)d_in[3];
    const float* b_hh0_f = (const float*)d_in[4];
    const float* w_ih0_b = (const float*)d_in[5];
    const float* w_hh0_b = (const float*)d_in[6];
    const float* b_ih0_b = (const float*)d_in[7];
    const float* b_hh0_b = (const float*)d_in[8];
    const float* w_ih1_f = (const float*)d_in[9];
    const float* w_hh1_f = (const float*)d_in[10];
    const float* b_ih1_f = (const float*)d_in[11];
    const float* b_hh1_f = (const float*)d_in[12];
    const float* w_ih1_b = (const float*)d_in[13];
    const float* w_hh1_b = (const float*)d_in[14];
    const float* b_ih1_b = (const float*)d_in[15];
    const float* b_hh1_b = (const float*)d_in[16];
    float* out = (float*)d_out;

    float *xg_f, *xg_b, *l0;
    cudaGetSymbolAddress((void**)&xg_f, g_xg_f);
    cudaGetSymbolAddress((void**)&xg_b, g_xg_b);
    cudaGetSymbolAddress((void**)&l0,   g_l0);

    cudaFuncSetAttribute(lstm_persist,
                         cudaFuncAttributeMaxDynamicSharedMemorySize, SMEM_BYTES);

    const dim3 gemm_grid(G4 / 128, MROWS / 128);   // (16, 256)

    // ---- layer 0 ----
    sgemm_bias<<<gemm_grid, 256>>>(x, w_ih0_f, b_ih0_f, b_hh0_f, xg_f, 512, G4);
    sgemm_bias<<<gemm_grid, 256>>>(x, w_ih0_b, b_ih0_b, b_hh0_b, xg_b, 512, G4);
    init_state<<<128, 256>>>();
    lstm_persist<<<NBLK, 256, SMEM_BYTES>>>(xg_f, xg_b, w_hh0_f, w_hh0_b, l0);

    // ---- layer 1 (K = 1024) ----
    sgemm_bias<<<gemm_grid, 256>>>(l0, w_ih1_f, b_ih1_f, b_hh1_f, xg_f, 1024, G4);
    sgemm_bias<<<gemm_grid, 256>>>(l0, w_ih1_b, b_ih1_b, b_hh1_b, xg_b, 1024, G4);
    init_state<<<128, 256>>>();
    lstm_persist<<<NBLK, 256, SMEM_BYTES>>>(xg_f, xg_b, w_hh1_f, w_hh1_b, out);
}